// round 16
// baseline (speedup 1.0000x reference)
#include <cuda_runtime.h>
#include <cuda_fp16.h>

#define D 64
#define MAX_NODES 150016
#define MAX_EDGES 2100000
#define SCAN_B 512
#define MAX_BLKS ((MAX_NODES + SCAN_B - 1) / SCAN_B)

// Static scratch (allocation-free rule). Kernels bind these symbols directly.
__device__ __half g_h0[(size_t)MAX_NODES * D];  // x0 concat (fp16)
__device__ __half g_h1[(size_t)MAX_NODES * D];  // x1 (fp16)
__device__ __half g_h2[(size_t)MAX_NODES * D];  // x2 (fp16)
__device__ int    g_cnt[MAX_NODES];             // per-dst edge counts
__device__ int    g_off[MAX_NODES + 1];         // CSR offsets
__device__ int    g_cur[MAX_NODES];             // scatter cursors
__device__ int    g_bagg[MAX_BLKS];             // lookback: block aggregates
__device__ int    g_bincl[MAX_BLKS];            // lookback: inclusive prefixes
__device__ int    g_sstat[MAX_BLKS];            // lookback: 0=none,1=agg,2=incl
__device__ int2   g_edge[MAX_EDGES];            // dst-grouped packed (src, w-bits)

__device__ __forceinline__ void h4_store(__half* p, float4 v) {
    __half2 h0 = __floats2half2_rn(v.x, v.y);
    __half2 h1 = __floats2half2_rn(v.z, v.w);
    uint2 u;
    u.x = *(const unsigned int*)&h0;
    u.y = *(const unsigned int*)&h1;
    *(uint2*)p = u;
}
__device__ __forceinline__ float4 h4_load(const __half* p) {
    uint2 u = *(const uint2*)p;
    float2 f0 = __half22float2(*(const __half2*)&u.x);
    float2 f1 = __half22float2(*(const __half2*)&u.y);
    return make_float4(f0.x, f0.y, f1.x, f1.y);
}
__device__ __forceinline__ void h8_store(__half* p, float4 a, float4 b) {
    __half2 h0 = __floats2half2_rn(a.x, a.y);
    __half2 h1 = __floats2half2_rn(a.z, a.w);
    __half2 h2 = __floats2half2_rn(b.x, b.y);
    __half2 h3 = __floats2half2_rn(b.z, b.w);
    uint4 u;
    u.x = *(const unsigned int*)&h0;
    u.y = *(const unsigned int*)&h1;
    u.z = *(const unsigned int*)&h2;
    u.w = *(const unsigned int*)&h3;
    *(uint4*)p = u;
}
__device__ __forceinline__ void fma8(uint4 u, float w, float4& a, float4& b) {
    float2 f0 = __half22float2(*(const __half2*)&u.x);
    float2 f1 = __half22float2(*(const __half2*)&u.y);
    float2 f2 = __half22float2(*(const __half2*)&u.z);
    float2 f3 = __half22float2(*(const __half2*)&u.w);
    a.x += w * f0.x; a.y += w * f0.y; a.z += w * f1.x; a.w += w * f1.y;
    b.x += w * f2.x; b.y += w * f2.y; b.z += w * f3.x; b.w += w * f3.y;
}

// Concatenate embeddings into g_h0 (fp16 x0); zero hist counts + scan status.
__global__ void init_kernel(const float* __restrict__ ue,
                            const float* __restrict__ ie,
                            int n_user_f, int n4, int n_nodes, int nblk) {
    int i = blockIdx.x * blockDim.x + threadIdx.x;   // float4 index
    if (i < n_nodes) g_cnt[i] = 0;
    if (i < nblk)    g_sstat[i] = 0;
    if (i >= n4) return;
    int f = i << 2;
    float4 v = (f < n_user_f) ? ((const float4*)ue)[i]
                              : ((const float4*)ie)[i - (n_user_f >> 2)];
    h4_store(g_h0 + ((size_t)i << 2), v);
}

// Histogram, 4 edges per thread (int4 loads).
__global__ void hist_kernel(const int* __restrict__ dst, int n_edges) {
    int i = blockIdx.x * blockDim.x + threadIdx.x;
    int base = i << 2;
    if (base >= n_edges) return;
    if (base + 4 <= n_edges) {
        int4 d = *(const int4*)(dst + base);
        atomicAdd(&g_cnt[d.x], 1);
        atomicAdd(&g_cnt[d.y], 1);
        atomicAdd(&g_cnt[d.z], 1);
        atomicAdd(&g_cnt[d.w], 1);
    } else {
        for (int e = base; e < n_edges; e++) atomicAdd(&g_cnt[dst[e]], 1);
    }
}

// Block-wide inclusive scan of one int per thread (SCAN_B threads).
__device__ __forceinline__ int block_incl_scan(int v) {
    __shared__ int wsum[SCAN_B / 32];
    int lane = threadIdx.x & 31;
    int wid  = threadIdx.x >> 5;
    int x = v;
    #pragma unroll
    for (int o = 1; o < 32; o <<= 1) {
        int t = __shfl_up_sync(0xffffffffu, x, o);
        if (lane >= o) x += t;
    }
    if (lane == 31) wsum[wid] = x;
    __syncthreads();
    if (wid == 0) {
        int w = (lane < SCAN_B / 32) ? wsum[lane] : 0;
        #pragma unroll
        for (int o = 1; o < SCAN_B / 32; o <<= 1) {
            int t = __shfl_up_sync(0xffffffffu, w, o);
            if (lane >= o) w += t;
        }
        if (lane < SCAN_B / 32) wsum[lane] = w;
    }
    __syncthreads();
    return x + (wid ? wsum[wid - 1] : 0);
}

// Single-pass decoupled-lookback exclusive scan: g_cnt -> g_off/g_cur.
__global__ void scan_kernel(int n, int nblk) {
    int b = blockIdx.x;
    int i = b * SCAN_B + threadIdx.x;
    int v = (i < n) ? g_cnt[i] : 0;
    int inc = block_incl_scan(v);
    __shared__ int sh_total;
    __shared__ int sh_ex;
    if (threadIdx.x == SCAN_B - 1) sh_total = inc;
    __syncthreads();
    int total = sh_total;
    if (threadIdx.x == 0) {
        if (b == 0) {
            g_bincl[0] = total;
            __threadfence();
            atomicExch(&g_sstat[0], 2);
            sh_ex = 0;
        } else {
            g_bagg[b] = total;
            __threadfence();
            atomicExch(&g_sstat[b], 1);
            int sum = 0, j = b - 1;
            while (true) {
                int st;
                while ((st = atomicAdd(&g_sstat[j], 0)) == 0) {}
                __threadfence();
                if (st == 2) { sum += g_bincl[j]; break; }
                sum += g_bagg[j];
                j--;
            }
            g_bincl[b] = sum + total;
            __threadfence();
            atomicExch(&g_sstat[b], 2);
            sh_ex = sum;
        }
    }
    __syncthreads();
    int ex = sh_ex;
    if (i < n) {
        int o = ex + inc - v;
        g_off[i] = o;
        g_cur[i] = o;
    }
    if (b == nblk - 1 && threadIdx.x == SCAN_B - 1) g_off[n] = ex + inc;
}

// Scatter, 4 edges per thread (int4/float4 loads).
__global__ void scatter_kernel(const int* __restrict__ src,
                               const int* __restrict__ dst,
                               const float* __restrict__ w, int n_edges) {
    int i = blockIdx.x * blockDim.x + threadIdx.x;
    int base = i << 2;
    if (base >= n_edges) return;
    if (base + 4 <= n_edges) {
        int4   s = *(const int4*)  (src + base);
        int4   d = *(const int4*)  (dst + base);
        float4 v = *(const float4*)(w   + base);
        int p;
        p = atomicAdd(&g_cur[d.x], 1); g_edge[p] = make_int2(s.x, __float_as_int(v.x));
        p = atomicAdd(&g_cur[d.y], 1); g_edge[p] = make_int2(s.y, __float_as_int(v.y));
        p = atomicAdd(&g_cur[d.z], 1); g_edge[p] = make_int2(s.z, __float_as_int(v.z));
        p = atomicAdd(&g_cur[d.w], 1); g_edge[p] = make_int2(s.w, __float_as_int(v.w));
    } else {
        for (int e = base; e < n_edges; e++) {
            int p = atomicAdd(&g_cur[dst[e]], 1);
            g_edge[p] = make_int2(src[e], __float_as_int(w[e]));
        }
    }
}

// Row-gather (fp16 source), 8 thr/node, 16B loads, 4-deep unroll + remainder.
__device__ __forceinline__ void row_gather8(const __half* __restrict__ x,
                                            int node, int c,
                                            float4& a0, float4& a1) {
    int beg = g_off[node];
    int end = g_off[node + 1];
    a0 = make_float4(0.f, 0.f, 0.f, 0.f);
    a1 = make_float4(0.f, 0.f, 0.f, 0.f);
    int i = beg;
    for (; i + 4 <= end; i += 4) {
        int2 p0 = g_edge[i];
        int2 p1 = g_edge[i + 1];
        int2 p2 = g_edge[i + 2];
        int2 p3 = g_edge[i + 3];
        uint4 u0 = *(const uint4*)(x + (size_t)p0.x * D + c);
        uint4 u1 = *(const uint4*)(x + (size_t)p1.x * D + c);
        uint4 u2 = *(const uint4*)(x + (size_t)p2.x * D + c);
        uint4 u3 = *(const uint4*)(x + (size_t)p3.x * D + c);
        fma8(u0, __int_as_float(p0.y), a0, a1);
        fma8(u1, __int_as_float(p1.y), a0, a1);
        fma8(u2, __int_as_float(p2.y), a0, a1);
        fma8(u3, __int_as_float(p3.y), a0, a1);
    }
    for (; i < end; i++) {
        int2 p = g_edge[i];
        uint4 u = *(const uint4*)(x + (size_t)p.x * D + c);
        fma8(u, __int_as_float(p.y), a0, a1);
    }
}

// Row-gather (fp16 source), 16 thr/node variant (8B loads), for fused score.
__device__ __forceinline__ float4 row_gather16(const __half* __restrict__ x,
                                               int node, int c) {
    int beg = g_off[node];
    int end = g_off[node + 1];
    float4 a = make_float4(0.f, 0.f, 0.f, 0.f);
    int i = beg;
    for (; i + 4 <= end; i += 4) {
        int2 p0 = g_edge[i];
        int2 p1 = g_edge[i + 1];
        int2 p2 = g_edge[i + 2];
        int2 p3 = g_edge[i + 3];
        float4 v0 = h4_load(x + (size_t)p0.x * D + c);
        float4 v1 = h4_load(x + (size_t)p1.x * D + c);
        float4 v2 = h4_load(x + (size_t)p2.x * D + c);
        float4 v3 = h4_load(x + (size_t)p3.x * D + c);
        float w0 = __int_as_float(p0.y);
        float w1 = __int_as_float(p1.y);
        float w2 = __int_as_float(p2.y);
        float w3 = __int_as_float(p3.y);
        a.x += w0 * v0.x + w1 * v1.x + w2 * v2.x + w3 * v3.x;
        a.y += w0 * v0.y + w1 * v1.y + w2 * v2.y + w3 * v3.y;
        a.z += w0 * v0.z + w1 * v1.z + w2 * v2.z + w3 * v3.z;
        a.w += w0 * v0.w + w1 * v1.w + w2 * v2.w + w3 * v3.w;
    }
    for (; i < end; i++) {
        int2 p = g_edge[i];
        float4 v = h4_load(x + (size_t)p.x * D + c);
        float ww = __int_as_float(p.y);
        a.x += ww * v.x; a.y += ww * v.y; a.z += ww * v.z; a.w += ww * v.w;
    }
    return a;
}

// Dense SpMM, fp16 -> fp16, 8 threads/node. which=0: h0->h1; 1: h1->h2.
__global__ void spmm_h2h_kernel(int n_nodes, int which) {
    const __half* __restrict__ x = which ? g_h1 : g_h0;
    __half*                    y = which ? g_h2 : g_h1;
    int t = blockIdx.x * blockDim.x + threadIdx.x;
    int node = t >> 3;
    if (node >= n_nodes) return;
    int c = (t & 7) << 3;                  // half offset: 0..56
    float4 a0, a1;
    row_gather8(x, node, c, a0, a1);
    h8_store(y + (size_t)node * D + c, a0, a1);
}

// Fused layer-3 + score: one warp per pair. Lanes 0-15 handle the user node,
// lanes 16-31 the item node; each lane owns 4 dims. x3 is gathered on the
// fly from g_h2 (never materialized). Final row = (x0+x1+x2+x3)/4 with the
// 1/16 folded into the dot product.
__global__ void score_kernel(const float* __restrict__ ue,
                             const float* __restrict__ ie,
                             const int* __restrict__ users,
                             const int* __restrict__ items,
                             float* __restrict__ out, int B, int n_users) {
    int g    = blockIdx.x * blockDim.x + threadIdx.x;
    int pair = g >> 5;
    int lane = threadIdx.x & 31;
    if (pair >= B) return;
    int  l       = lane & 15;
    bool is_item = lane >= 16;
    int  idx     = is_item ? items[pair] : users[pair];
    int  node    = is_item ? (n_users + idx) : idx;
    int  c       = l << 2;                 // half/float offset within row
    // x3 slice (fp32 accumulation, exactly as the old list kernel)
    float4 a = row_gather16(g_h2, node, c);
    // x0 slice exact fp32 from the original inputs
    const float* b0 = is_item ? (ie + (size_t)idx * D) : (ue + (size_t)idx * D);
    float4 x0 = *(const float4*)(b0 + c);
    float4 x1 = h4_load(g_h1 + (size_t)node * D + c);
    float4 x2 = h4_load(g_h2 + (size_t)node * D + c);
    float4 F = make_float4(x0.x + x1.x + x2.x + a.x,
                           x0.y + x1.y + x2.y + a.y,
                           x0.z + x1.z + x2.z + a.z,
                           x0.w + x1.w + x2.w + a.w);
    // bring the item slice (lane l+16) to the user lane l
    float vx = __shfl_sync(0xffffffffu, F.x, lane + 16);
    float vy = __shfl_sync(0xffffffffu, F.y, lane + 16);
    float vz = __shfl_sync(0xffffffffu, F.z, lane + 16);
    float vw = __shfl_sync(0xffffffffu, F.w, lane + 16);
    float s = F.x * vx + F.y * vy + F.z * vz + F.w * vw;
    #pragma unroll
    for (int o = 8; o; o >>= 1) s += __shfl_xor_sync(0xffffffffu, s, o);
    if (lane == 0) out[pair] = s * (1.0f / 16.0f);
}

extern "C" void kernel_launch(void* const* d_in, const int* in_sizes, int n_in,
                              void* d_out, int out_size) {
    const float* ue    = (const float*)d_in[0];
    const float* ie    = (const float*)d_in[1];
    const int*   esrc  = (const int*)  d_in[2];
    const int*   edst  = (const int*)  d_in[3];
    const float* ew    = (const float*)d_in[4];
    const int*   users = (const int*)  d_in[5];
    const int*   items = (const int*)  d_in[6];

    int n_user_f  = in_sizes[0];
    int n_item_f  = in_sizes[1];
    int n_edges   = in_sizes[2];
    int B         = in_sizes[5];
    int n_total_f = n_user_f + n_item_f;
    int n_users   = n_user_f / D;
    int n_nodes   = n_total_f / D;
    int n4        = n_total_f >> 2;
    int nblk      = (n_nodes + SCAN_B - 1) / SCAN_B;
    int ne4       = (n_edges + 3) >> 2;

    init_kernel<<<(n4 + 255) / 256, 256>>>(ue, ie, n_user_f, n4, n_nodes, nblk);
    hist_kernel<<<(ne4 + 255) / 256, 256>>>(edst, n_edges);
    scan_kernel<<<nblk, SCAN_B>>>(n_nodes, nblk);
    scatter_kernel<<<(ne4 + 255) / 256, 256>>>(esrc, edst, ew, n_edges);

    long long td = (long long)n_nodes * 8;
    int gd = (int)((td + 255) / 256);
    spmm_h2h_kernel<<<gd, 256>>>(n_nodes, 0);           // x1 = A x0
    spmm_h2h_kernel<<<gd, 256>>>(n_nodes, 1);           // x2 = A x1

    score_kernel<<<(B * 32 + 255) / 256, 256>>>(ue, ie, users, items,
                                                (float*)d_out, B, n_users);
}

// round 17
// speedup vs baseline: 1.0130x; 1.0130x over previous
#include <cuda_runtime.h>
#include <cuda_fp16.h>

#define D 64
#define MAX_NODES 150016
#define MAX_EDGES 2100000
#define SCAN_B 512
#define MAX_BLKS ((MAX_NODES + SCAN_B - 1) / SCAN_B)

// Static scratch (allocation-free rule). Kernels bind these symbols directly.
__device__ __half g_h0[(size_t)MAX_NODES * D];  // x0 concat (fp16)
__device__ __half g_h1[(size_t)MAX_NODES * D];  // x1 (fp16)
__device__ __half g_h2[(size_t)MAX_NODES * D];  // x2 (fp16)
__device__ int    g_cnt[MAX_NODES];             // per-dst edge counts
__device__ int    g_off[MAX_NODES + 1];         // CSR offsets
__device__ int    g_cur[MAX_NODES];             // scatter cursors
__device__ int    g_bagg[MAX_BLKS];             // lookback: block aggregates
__device__ int    g_bincl[MAX_BLKS];            // lookback: inclusive prefixes
__device__ int    g_sstat[MAX_BLKS];            // lookback: 0=none,1=agg,2=incl
__device__ int2   g_edge[MAX_EDGES];            // dst-grouped packed (src, w-bits)

__device__ __forceinline__ void h4_store(__half* p, float4 v) {
    __half2 h0 = __floats2half2_rn(v.x, v.y);
    __half2 h1 = __floats2half2_rn(v.z, v.w);
    uint2 u;
    u.x = *(const unsigned int*)&h0;
    u.y = *(const unsigned int*)&h1;
    *(uint2*)p = u;
}
__device__ __forceinline__ float4 h4_load(const __half* p) {
    uint2 u = *(const uint2*)p;
    float2 f0 = __half22float2(*(const __half2*)&u.x);
    float2 f1 = __half22float2(*(const __half2*)&u.y);
    return make_float4(f0.x, f0.y, f1.x, f1.y);
}
__device__ __forceinline__ void h8_store(__half* p, float4 a, float4 b) {
    __half2 h0 = __floats2half2_rn(a.x, a.y);
    __half2 h1 = __floats2half2_rn(a.z, a.w);
    __half2 h2 = __floats2half2_rn(b.x, b.y);
    __half2 h3 = __floats2half2_rn(b.z, b.w);
    uint4 u;
    u.x = *(const unsigned int*)&h0;
    u.y = *(const unsigned int*)&h1;
    u.z = *(const unsigned int*)&h2;
    u.w = *(const unsigned int*)&h3;
    *(uint4*)p = u;
}
__device__ __forceinline__ void fma8(uint4 u, float w, float4& a, float4& b) {
    float2 f0 = __half22float2(*(const __half2*)&u.x);
    float2 f1 = __half22float2(*(const __half2*)&u.y);
    float2 f2 = __half22float2(*(const __half2*)&u.z);
    float2 f3 = __half22float2(*(const __half2*)&u.w);
    a.x += w * f0.x; a.y += w * f0.y; a.z += w * f1.x; a.w += w * f1.y;
    b.x += w * f2.x; b.y += w * f2.y; b.z += w * f3.x; b.w += w * f3.y;
}

// Concatenate embeddings into g_h0 (fp16 x0); zero hist counts + scan status.
__global__ void init_kernel(const float* __restrict__ ue,
                            const float* __restrict__ ie,
                            int n_user_f, int n4, int n_nodes, int nblk) {
    int i = blockIdx.x * blockDim.x + threadIdx.x;   // float4 index
    if (i < n_nodes) g_cnt[i] = 0;
    if (i < nblk)    g_sstat[i] = 0;
    if (i >= n4) return;
    int f = i << 2;
    float4 v = (f < n_user_f) ? ((const float4*)ue)[i]
                              : ((const float4*)ie)[i - (n_user_f >> 2)];
    h4_store(g_h0 + ((size_t)i << 2), v);
}

// Histogram, 4 edges per thread (int4 loads).
__global__ void hist_kernel(const int* __restrict__ dst, int n_edges) {
    int i = blockIdx.x * blockDim.x + threadIdx.x;
    int base = i << 2;
    if (base >= n_edges) return;
    if (base + 4 <= n_edges) {
        int4 d = *(const int4*)(dst + base);
        atomicAdd(&g_cnt[d.x], 1);
        atomicAdd(&g_cnt[d.y], 1);
        atomicAdd(&g_cnt[d.z], 1);
        atomicAdd(&g_cnt[d.w], 1);
    } else {
        for (int e = base; e < n_edges; e++) atomicAdd(&g_cnt[dst[e]], 1);
    }
}

// Block-wide inclusive scan of one int per thread (SCAN_B threads).
__device__ __forceinline__ int block_incl_scan(int v) {
    __shared__ int wsum[SCAN_B / 32];
    int lane = threadIdx.x & 31;
    int wid  = threadIdx.x >> 5;
    int x = v;
    #pragma unroll
    for (int o = 1; o < 32; o <<= 1) {
        int t = __shfl_up_sync(0xffffffffu, x, o);
        if (lane >= o) x += t;
    }
    if (lane == 31) wsum[wid] = x;
    __syncthreads();
    if (wid == 0) {
        int w = (lane < SCAN_B / 32) ? wsum[lane] : 0;
        #pragma unroll
        for (int o = 1; o < SCAN_B / 32; o <<= 1) {
            int t = __shfl_up_sync(0xffffffffu, w, o);
            if (lane >= o) w += t;
        }
        if (lane < SCAN_B / 32) wsum[lane] = w;
    }
    __syncthreads();
    return x + (wid ? wsum[wid - 1] : 0);
}

// Single-pass decoupled-lookback exclusive scan: g_cnt -> g_off/g_cur.
__global__ void scan_kernel(int n, int nblk) {
    int b = blockIdx.x;
    int i = b * SCAN_B + threadIdx.x;
    int v = (i < n) ? g_cnt[i] : 0;
    int inc = block_incl_scan(v);
    __shared__ int sh_total;
    __shared__ int sh_ex;
    if (threadIdx.x == SCAN_B - 1) sh_total = inc;
    __syncthreads();
    int total = sh_total;
    if (threadIdx.x == 0) {
        if (b == 0) {
            g_bincl[0] = total;
            __threadfence();
            atomicExch(&g_sstat[0], 2);
            sh_ex = 0;
        } else {
            g_bagg[b] = total;
            __threadfence();
            atomicExch(&g_sstat[b], 1);
            int sum = 0, j = b - 1;
            while (true) {
                int st;
                while ((st = atomicAdd(&g_sstat[j], 0)) == 0) {}
                __threadfence();
                if (st == 2) { sum += g_bincl[j]; break; }
                sum += g_bagg[j];
                j--;
            }
            g_bincl[b] = sum + total;
            __threadfence();
            atomicExch(&g_sstat[b], 2);
            sh_ex = sum;
        }
    }
    __syncthreads();
    int ex = sh_ex;
    if (i < n) {
        int o = ex + inc - v;
        g_off[i] = o;
        g_cur[i] = o;
    }
    if (b == nblk - 1 && threadIdx.x == SCAN_B - 1) g_off[n] = ex + inc;
}

// Scatter, 4 edges per thread (int4/float4 loads).
__global__ void scatter_kernel(const int* __restrict__ src,
                               const int* __restrict__ dst,
                               const float* __restrict__ w, int n_edges) {
    int i = blockIdx.x * blockDim.x + threadIdx.x;
    int base = i << 2;
    if (base >= n_edges) return;
    if (base + 4 <= n_edges) {
        int4   s = *(const int4*)  (src + base);
        int4   d = *(const int4*)  (dst + base);
        float4 v = *(const float4*)(w   + base);
        int p;
        p = atomicAdd(&g_cur[d.x], 1); g_edge[p] = make_int2(s.x, __float_as_int(v.x));
        p = atomicAdd(&g_cur[d.y], 1); g_edge[p] = make_int2(s.y, __float_as_int(v.y));
        p = atomicAdd(&g_cur[d.z], 1); g_edge[p] = make_int2(s.z, __float_as_int(v.z));
        p = atomicAdd(&g_cur[d.w], 1); g_edge[p] = make_int2(s.w, __float_as_int(v.w));
    } else {
        for (int e = base; e < n_edges; e++) {
            int p = atomicAdd(&g_cur[dst[e]], 1);
            g_edge[p] = make_int2(src[e], __float_as_int(w[e]));
        }
    }
}

// Row-gather (fp16 source), 8 thr/node, 16B loads, 4-deep unroll + remainder.
__device__ __forceinline__ void row_gather8(const __half* __restrict__ x,
                                            int node, int c,
                                            float4& a0, float4& a1) {
    int beg = g_off[node];
    int end = g_off[node + 1];
    a0 = make_float4(0.f, 0.f, 0.f, 0.f);
    a1 = make_float4(0.f, 0.f, 0.f, 0.f);
    int i = beg;
    for (; i + 4 <= end; i += 4) {
        int2 p0 = g_edge[i];
        int2 p1 = g_edge[i + 1];
        int2 p2 = g_edge[i + 2];
        int2 p3 = g_edge[i + 3];
        uint4 u0 = *(const uint4*)(x + (size_t)p0.x * D + c);
        uint4 u1 = *(const uint4*)(x + (size_t)p1.x * D + c);
        uint4 u2 = *(const uint4*)(x + (size_t)p2.x * D + c);
        uint4 u3 = *(const uint4*)(x + (size_t)p3.x * D + c);
        fma8(u0, __int_as_float(p0.y), a0, a1);
        fma8(u1, __int_as_float(p1.y), a0, a1);
        fma8(u2, __int_as_float(p2.y), a0, a1);
        fma8(u3, __int_as_float(p3.y), a0, a1);
    }
    for (; i < end; i++) {
        int2 p = g_edge[i];
        uint4 u = *(const uint4*)(x + (size_t)p.x * D + c);
        fma8(u, __int_as_float(p.y), a0, a1);
    }
}

// Row-gather (fp16 source), 16 thr/node variant (8B loads), for fused score.
__device__ __forceinline__ float4 row_gather16(const __half* __restrict__ x,
                                               int node, int c) {
    int beg = g_off[node];
    int end = g_off[node + 1];
    float4 a = make_float4(0.f, 0.f, 0.f, 0.f);
    int i = beg;
    for (; i + 4 <= end; i += 4) {
        int2 p0 = g_edge[i];
        int2 p1 = g_edge[i + 1];
        int2 p2 = g_edge[i + 2];
        int2 p3 = g_edge[i + 3];
        float4 v0 = h4_load(x + (size_t)p0.x * D + c);
        float4 v1 = h4_load(x + (size_t)p1.x * D + c);
        float4 v2 = h4_load(x + (size_t)p2.x * D + c);
        float4 v3 = h4_load(x + (size_t)p3.x * D + c);
        float w0 = __int_as_float(p0.y);
        float w1 = __int_as_float(p1.y);
        float w2 = __int_as_float(p2.y);
        float w3 = __int_as_float(p3.y);
        a.x += w0 * v0.x + w1 * v1.x + w2 * v2.x + w3 * v3.x;
        a.y += w0 * v0.y + w1 * v1.y + w2 * v2.y + w3 * v3.y;
        a.z += w0 * v0.z + w1 * v1.z + w2 * v2.z + w3 * v3.z;
        a.w += w0 * v0.w + w1 * v1.w + w2 * v2.w + w3 * v3.w;
    }
    for (; i < end; i++) {
        int2 p = g_edge[i];
        float4 v = h4_load(x + (size_t)p.x * D + c);
        float ww = __int_as_float(p.y);
        a.x += ww * v.x; a.y += ww * v.y; a.z += ww * v.z; a.w += ww * v.w;
    }
    return a;
}

// Dense SpMM, fp16 -> fp16, 8 threads/node. which=0: h0->h1; 1: h1->h2.
__global__ void spmm_h2h_kernel(int n_nodes, int which) {
    const __half* __restrict__ x = which ? g_h1 : g_h0;
    __half*                    y = which ? g_h2 : g_h1;
    int t = blockIdx.x * blockDim.x + threadIdx.x;
    int node = t >> 3;
    if (node >= n_nodes) return;
    int c = (t & 7) << 3;                  // half offset: 0..56
    float4 a0, a1;
    row_gather8(x, node, c, a0, a1);
    h8_store(y + (size_t)node * D + c, a0, a1);
}

// Fused layer-3 + score: one warp per pair. Lanes 0-15 handle the user node,
// lanes 16-31 the item node; each lane owns 4 dims. x3 is gathered on the
// fly from g_h2 (never materialized). Final row = (x0+x1+x2+x3)/4 with the
// 1/16 folded into the dot product.
__global__ void score_kernel(const float* __restrict__ ue,
                             const float* __restrict__ ie,
                             const int* __restrict__ users,
                             const int* __restrict__ items,
                             float* __restrict__ out, int B, int n_users) {
    int g    = blockIdx.x * blockDim.x + threadIdx.x;
    int pair = g >> 5;
    int lane = threadIdx.x & 31;
    if (pair >= B) return;
    int  l       = lane & 15;
    bool is_item = lane >= 16;
    int  idx     = is_item ? items[pair] : users[pair];
    int  node    = is_item ? (n_users + idx) : idx;
    int  c       = l << 2;                 // half/float offset within row
    // x3 slice (fp32 accumulation, exactly as the old list kernel)
    float4 a = row_gather16(g_h2, node, c);
    // x0 slice exact fp32 from the original inputs
    const float* b0 = is_item ? (ie + (size_t)idx * D) : (ue + (size_t)idx * D);
    float4 x0 = *(const float4*)(b0 + c);
    float4 x1 = h4_load(g_h1 + (size_t)node * D + c);
    float4 x2 = h4_load(g_h2 + (size_t)node * D + c);
    float4 F = make_float4(x0.x + x1.x + x2.x + a.x,
                           x0.y + x1.y + x2.y + a.y,
                           x0.z + x1.z + x2.z + a.z,
                           x0.w + x1.w + x2.w + a.w);
    // bring the item slice (lane l+16) to the user lane l
    float vx = __shfl_sync(0xffffffffu, F.x, lane + 16);
    float vy = __shfl_sync(0xffffffffu, F.y, lane + 16);
    float vz = __shfl_sync(0xffffffffu, F.z, lane + 16);
    float vw = __shfl_sync(0xffffffffu, F.w, lane + 16);
    float s = F.x * vx + F.y * vy + F.z * vz + F.w * vw;
    #pragma unroll
    for (int o = 8; o; o >>= 1) s += __shfl_xor_sync(0xffffffffu, s, o);
    if (lane == 0) out[pair] = s * (1.0f / 16.0f);
}

extern "C" void kernel_launch(void* const* d_in, const int* in_sizes, int n_in,
                              void* d_out, int out_size) {
    const float* ue    = (const float*)d_in[0];
    const float* ie    = (const float*)d_in[1];
    const int*   esrc  = (const int*)  d_in[2];
    const int*   edst  = (const int*)  d_in[3];
    const float* ew    = (const float*)d_in[4];
    const int*   users = (const int*)  d_in[5];
    const int*   items = (const int*)  d_in[6];

    int n_user_f  = in_sizes[0];
    int n_item_f  = in_sizes[1];
    int n_edges   = in_sizes[2];
    int B         = in_sizes[5];
    int n_total_f = n_user_f + n_item_f;
    int n_users   = n_user_f / D;
    int n_nodes   = n_total_f / D;
    int n4        = n_total_f >> 2;
    int nblk      = (n_nodes + SCAN_B - 1) / SCAN_B;
    int ne4       = (n_edges + 3) >> 2;

    init_kernel<<<(n4 + 255) / 256, 256>>>(ue, ie, n_user_f, n4, n_nodes, nblk);
    hist_kernel<<<(ne4 + 255) / 256, 256>>>(edst, n_edges);
    scan_kernel<<<nblk, SCAN_B>>>(n_nodes, nblk);
    scatter_kernel<<<(ne4 + 255) / 256, 256>>>(esrc, edst, ew, n_edges);

    long long td = (long long)n_nodes * 8;
    int gd = (int)((td + 255) / 256);
    spmm_h2h_kernel<<<gd, 256>>>(n_nodes, 0);           // x1 = A x0
    spmm_h2h_kernel<<<gd, 256>>>(n_nodes, 1);           // x2 = A x1

    score_kernel<<<(B * 32 + 255) / 256, 256>>>(ue, ie, users, items,
                                                (float*)d_out, B, n_users);
}